// round 10
// baseline (speedup 1.0000x reference)
#include <cuda_runtime.h>
#include <cstdint>

#define N     8192
#define K1    31
#define CAP   256      // per-line candidate capacity (mean 88, max ~135)
#define PIVOT 2.3f     // P(z>2.3)=0.0107
#define NF4   ((size_t)N * N / 4)
#define FULLM 0xFFFFFFFFu

__device__ unsigned int       g_bits[(size_t)N * N / 32];  // 8 MB candidate bitmask
__device__ unsigned long long g_colcand[(size_t)N * CAP];  // 16 MB
__device__ int                g_colcnt[N];
__device__ unsigned long long g_rowth[N];

// Monotone map float -> uint32 (larger float => larger key)
__device__ __forceinline__ unsigned int fkey(float x) {
    unsigned int u = __float_as_uint(x);
    return (u & 0x80000000u) ? ~u : (u | 0x80000000u);
}
__device__ __forceinline__ float inv_fkey(unsigned int k) {
    unsigned int u = (k & 0x80000000u) ? (k ^ 0x80000000u) : ~k;
    return __uint_as_float(u);
}
// Composite key: value-major, lower index wins ties (stable top_k semantics)
__device__ __forceinline__ unsigned long long ckey(float x, int idx) {
    return ((unsigned long long)fkey(x) << 32) | (unsigned int)(N - 1 - idx);
}

// block-level exact fallback: K1-th largest key of a full line.
// Block-uniform (ALL threads of the block participate). Never triggered
// statistically; kept for exactness on arbitrary inputs.
template <bool ROW, int BT>
__device__ unsigned long long block_fallback(const float* __restrict__ A, int line) {
    __shared__ unsigned long long red[BT];
    unsigned long long prev = 0xFFFFFFFFFFFFFFFFull;
    for (int it = 0; it < K1; it++) {
        unsigned long long best = 0;
        for (int t = threadIdx.x; t < N; t += BT) {
            float x = ROW ? A[(size_t)line * N + t] : A[(size_t)t * N + line];
            unsigned long long k = ckey(x, t);
            if (k < prev && k > best) best = k;
        }
        red[threadIdx.x] = best;
        __syncthreads();
        for (int s = BT / 2; s > 0; s >>= 1) {
            if (threadIdx.x < s) {
                unsigned long long o = red[threadIdx.x + s];
                if (o > red[threadIdx.x]) red[threadIdx.x] = o;
            }
            __syncthreads();
        }
        prev = red[0];
        __syncthreads();
    }
    return prev;
}

// K1: PURE streaming pass (measured 81us @ 6.1TB/s). Reads A, zeros out,
// emits bitmask via ballots; first 32 blocks zero g_colcnt.
// Word i*256 + seg*4 + comp, bit b  <->  element (i, seg*128 + b*4 + comp).
__global__ __launch_bounds__(256) void stream_kernel(const float* __restrict__ A,
                                                     float* __restrict__ out) {
    if (blockIdx.x < N / 256) g_colcnt[blockIdx.x * 256 + threadIdx.x] = 0;
    const size_t g = (size_t)blockIdx.x * 256 + threadIdx.x;  // float4 index
    float4 v = ((const float4*)A)[g];
    const float4 zz = {0.0f, 0.0f, 0.0f, 0.0f};
    ((float4*)out)[g] = zz;
    unsigned m0 = __ballot_sync(FULLM, v.x > PIVOT);
    unsigned m1 = __ballot_sync(FULLM, v.y > PIVOT);
    unsigned m2 = __ballot_sync(FULLM, v.z > PIVOT);
    unsigned m3 = __ballot_sync(FULLM, v.w > PIVOT);
    if ((threadIdx.x & 31) == 0) {
        uint4 w = {m0, m1, m2, m3};
        ((uint4*)g_bits)[g >> 5] = w;
    }
}

// K2: TWO rows per block (512 threads = 2 x 256-thread halves).
// Decode bitmask, gather values, push column candidates (spread atomics),
// rank-count -> g_rowth. Two independent latency chains per block.
__global__ __launch_bounds__(512) void rowth_kernel(const float* __restrict__ A) {
    const int t = threadIdx.x, half = t >> 8, ht = t & 255;
    const int lane = t & 31, w = t >> 5;            // 16 warps
    const int row = blockIdx.x * 2 + half;
    __shared__ unsigned long long keys[2][CAP];
    __shared__ int wsum[16];
    __shared__ int s_total[2];

    unsigned wrd = g_bits[(size_t)row * 256 + ht];
    int cnt = __popc(wrd);
    int incl = cnt;
#pragma unroll
    for (int d = 1; d < 32; d <<= 1) {
        int v = __shfl_up_sync(FULLM, incl, d);
        if (lane >= d) incl += v;
    }
    if (lane == 31) wsum[w] = incl;
    __syncthreads();
    if (t < 2) {
        int s = 0;
#pragma unroll
        for (int k = 0; k < 8; k++) { int v = wsum[t * 8 + k]; wsum[t * 8 + k] = s; s += v; }
        s_total[t] = s;
    }
    __syncthreads();
    const int total = s_total[half];
    const bool ok = (total >= K1 && total <= CAP);
    int off = incl - cnt + wsum[w];

    // decode + gather + column push (always); smem store when healthy
    unsigned wb = wrd;
    const int seg = ht >> 2, comp = ht & 3;
    while (wb) {
        int b = __ffs(wb) - 1;
        wb &= wb - 1;
        int j = seg * 128 + b * 4 + comp;
        float x = A[(size_t)row * N + j];
        if (ok) keys[half][off] = ckey(x, j);
        off++;
        int cs = atomicAdd(&g_colcnt[j], 1);
        if (cs < CAP) g_colcand[(size_t)j * CAP + cs] = ckey(x, row);
    }
    __syncthreads();

    if (ok && ht < total) {
        unsigned long long kt = keys[half][ht];
        int r = 0;
        for (int m = 0; m < total; m++) r += (keys[half][m] > kt);
        if (r == K1 - 1) g_rowth[row] = kt;          // exactly one writer
    }
    // block-uniform rare fallback
    if (!(s_total[0] >= K1 && s_total[0] <= CAP)) {
        unsigned long long th = block_fallback<true, 512>(A, blockIdx.x * 2);
        if (t == 0) g_rowth[blockIdx.x * 2] = th;
    }
    if (!(s_total[1] >= K1 && s_total[1] <= CAP)) {
        unsigned long long th = block_fallback<true, 512>(A, blockIdx.x * 2 + 1);
        if (t == 0) g_rowth[blockIdx.x * 2 + 1] = th;
    }
}

// K3: TWO columns per block (256 threads = 2 x 128-thread halves).
// colth by rank-counting, then scatter survivors in-place.
__global__ __launch_bounds__(256) void colth_scatter_kernel(const float* __restrict__ A,
                                                            float* __restrict__ out) {
    const int t = threadIdx.x, half = t >> 7, ht = t & 127;
    const int j = blockIdx.x * 2 + half;
    __shared__ unsigned long long cand[2][CAP];
    __shared__ unsigned long long s_cth[2];
    __shared__ int s_c[2];

    if (ht == 0) s_c[half] = g_colcnt[j];
    __syncthreads();
    const int c = s_c[half];
    const bool ok = (c >= K1 && c <= CAP);

    if (ok) {
        for (int s = ht; s < c; s += 128)
            cand[half][s] = g_colcand[(size_t)j * CAP + s];
    }
    __syncthreads();
    if (ok) {
        for (int s = ht; s < c; s += 128) {
            unsigned long long kt = cand[half][s];
            int r = 0;
            for (int m = 0; m < c; m++) r += (cand[half][m] > kt);
            if (r == K1 - 1) s_cth[half] = kt;
        }
    }
    __syncthreads();
    if (ok) {
        const unsigned long long cth = s_cth[half];
        for (int s = ht; s < c; s += 128) {
            unsigned long long k = cand[half][s];
            if (k < cth) continue;
            int i = N - 1 - (int)(unsigned int)(k & 0xFFFFFFFFu);
            if (i == j) continue;
            float x = inv_fkey((unsigned int)(k >> 32));
            if (ckey(x, j) >= g_rowth[i])
                out[(size_t)i * N + j] = x;
        }
    }
    // block-uniform rare fallback: exact threshold + full-column rescan
#pragma unroll
    for (int h = 0; h < 2; h++) {
        if (!(s_c[h] >= K1 && s_c[h] <= CAP)) {
            const int jj = blockIdx.x * 2 + h;
            unsigned long long cth = block_fallback<false, 256>(A, jj);
            for (int i = t; i < N; i += 256) {
                if (i == jj) continue;
                float x = A[(size_t)i * N + jj];
                if (ckey(x, i) >= cth && ckey(x, jj) >= g_rowth[i])
                    out[(size_t)i * N + jj] = x;
            }
        }
    }
}

extern "C" void kernel_launch(void* const* d_in, const int* in_sizes, int n_in,
                              void* d_out, int out_size) {
    const float* A = (const float*)d_in[0];
    float* out = (float*)d_out;
    stream_kernel<<<(unsigned)(NF4 / 256), 256>>>(A, out);
    rowth_kernel<<<N / 2, 512>>>(A);
    colth_scatter_kernel<<<N / 2, 256>>>(A, out);
}